// round 6
// baseline (speedup 1.0000x reference)
#include <cuda_runtime.h>
#include <cuda_fp16.h>
#include <cstdint>
#include <cstddef>

// ---------------------------------------------------------------------------
// XOR-conv as implicit GEMM on warp-level mma.sync, single fp16 GEMM.
// out[b,co,ho,wo] = sum_{ci,kh,kw} (1-2W[co,ci,kh,kw]) * x[b,ci,ho+kh,wo+kw]
// Weights +-1 are exact in fp16; only fp16(x) quantization contributes error:
// predicted rel_err ~2e-4 (threshold 1e-3). f32 accumulation in HMMA.
// ---------------------------------------------------------------------------

#define BB 32
#define CIN 128
#define HH 64
#define WWD 64
#define COUT 256
#define HOUT 62
#define WOUT 62

// Preprocessed operands (static __device__ — no dynamic alloc)
__device__ __align__(16) uint16_t g_wbuf[9 * COUT * CIN];            // fp16 (1-2W), [khw][co][ci]
__device__ __align__(16) uint32_t g_xh[(size_t)BB * HH * WWD * 64];  // fp16x2 [b][h][w][ci/2]

// ---------------- helpers ----------------
__device__ __forceinline__ uint32_t smem_u32(const void* p) {
    uint32_t a;
    asm("{ .reg .u64 t; cvta.to.shared.u64 t, %1; cvt.u32.u64 %0, t; }" : "=r"(a) : "l"(p));
    return a;
}
__device__ __forceinline__ void cpa16(uint32_t dst, const void* src, uint32_t sz) {
    asm volatile("cp.async.cg.shared.global [%0], [%1], 16, %2;"
                 :: "r"(dst), "l"(src), "r"(sz) : "memory");
}
__device__ __forceinline__ void ldsm_x4(uint32_t* r, uint32_t a) {
    asm volatile("ldmatrix.sync.aligned.m8n8.x4.shared.b16 {%0,%1,%2,%3}, [%4];"
                 : "=r"(r[0]), "=r"(r[1]), "=r"(r[2]), "=r"(r[3]) : "r"(a));
}
#define MMA16816(c, A, b0, b1)                                                \
    asm volatile("mma.sync.aligned.m16n8k16.row.col.f32.f16.f16.f32 "         \
                 "{%0,%1,%2,%3}, {%4,%5,%6,%7}, {%8,%9}, {%0,%1,%2,%3};"      \
                 : "+f"((c)[0]), "+f"((c)[1]), "+f"((c)[2]), "+f"((c)[3])     \
                 : "r"((A)[0]), "r"((A)[1]), "r"((A)[2]), "r"((A)[3]),        \
                   "r"(b0), "r"(b1))

// ---------------- prep kernels ----------------
__global__ void prep_w_kernel(const float* __restrict__ w) {
    int idx = blockIdx.x * 256 + threadIdx.x;
    if (idx < 9 * COUT * CIN) {
        int khw = idx / (COUT * CIN);
        int rem = idx % (COUT * CIN);
        int co = rem >> 7, ci = rem & 127;
        int kh = khw / 3, kw = khw % 3;
        float v = 1.0f - 2.0f * w[(((size_t)co * CIN + ci) * 3 + kh) * 3 + kw];
        g_wbuf[idx] = __half_as_ushort(__float2half_rn(v));
    }
}

__global__ void prep_x_kernel(const float* __restrict__ x) {
    __shared__ float t[CIN][67];
    const int h = blockIdx.x, b = blockIdx.y, tid = threadIdx.x;
#pragma unroll
    for (int i = 0; i < 32; i++) {
        int idx = tid + i * 256;                      // [ci][w]
        int ci = idx >> 6, w = idx & 63;
        t[ci][w] = x[(((size_t)b * CIN + ci) * HH + h) * WWD + w];
    }
    __syncthreads();
#pragma unroll
    for (int i = 0; i < 16; i++) {
        int idx = tid + i * 256;                      // [w][ci-pair]
        int w = idx >> 6, j = idx & 63;
        uint32_t hw2 = ((uint32_t)__half_as_ushort(__float2half_rn(t[2 * j + 1][w])) << 16) |
                       __half_as_ushort(__float2half_rn(t[2 * j][w]));
        g_xh[(((size_t)b * HH + h) * WWD + w) * 64 + j] = hw2;
    }
}

// ---------------- main kernel ----------------
// smem: x: 2 bufs x (6*66*80) ; w: 4 bufs x (128*80)
#define POS_STRIDE 80
#define XBUFSZ (6 * 66 * POS_STRIDE)      // 31680
#define X_TOTAL (2 * XBUFSZ)              // 63360
#define WBUFSZ (128 * POS_STRIDE)         // 10240
#define SW_OFF X_TOTAL
#define SMEM_TOTAL (X_TOTAL + 4 * WBUFSZ) // 104320

__global__ __launch_bounds__(512, 1)
void xorconv_mma_kernel(float* __restrict__ out) {
    extern __shared__ char smraw[];
    const uint32_t SX = smem_u32(smraw);
    const uint32_t SW = SX + SW_OFF;

    const int tid = threadIdx.x;
    const int wid = tid >> 5, lid = tid & 31;
    const int wm = wid & 3;           // co sub-tile (32 rows)
    const int wn = wid >> 2;          // ho row 0..3
    const int ho0 = blockIdx.x * 4;
    const int co0 = blockIdx.y * 128;
    const int b = blockIdx.z;

    // ---- lane constants for ldmatrix addressing ----
    const int li = lid & 7, g = lid >> 3;
    // A (weights): [m0-7 k0-7, m8-15 k0-7, m0-7 k8-15, m8-15 k8-15]
    const uint32_t aoff0 = (uint32_t)(wm * 32 + 0 * 16 + (g & 1) * 8 + li) * POS_STRIDE + (g >> 1) * 16;
    const uint32_t aoff1 = (uint32_t)(wm * 32 + 1 * 16 + (g & 1) * 8 + li) * POS_STRIDE + (g >> 1) * 16;
    // B (x): [n0-7 k0-7, n0-7 k8-15, n8-15 k0-7, n8-15 k8-15]
    uint32_t qb[4];
#pragma unroll
    for (int j = 0; j < 4; j++)
        qb[j] = (uint32_t)(j * 16 + ((g >> 1) & 1) * 8 + li) * POS_STRIDE + (g & 1) * 16;

    float acc[2][8][4];
#pragma unroll
    for (int mi = 0; mi < 2; mi++)
#pragma unroll
        for (int ni = 0; ni < 8; ni++)
#pragma unroll
            for (int e = 0; e < 4; e++) acc[mi][ni][e] = 0.0f;

    // ---- staging ----
    auto stage_x = [&](int ci0q) {   // 32 ci (16 words), into xbuf[ci0q&1]
        const uint32_t xb = SX + (uint32_t)(ci0q & 1) * XBUFSZ;
#pragma unroll
        for (int i = 0; i < 4; i++) {
            int idx = tid + i * 512;
            if (idx < 1584) {
                int pos = idx >> 2, c4 = idx & 3;
                int hl = pos / 66, w = pos - hl * 66;
                int h = ho0 + hl;
                uint32_t sz = (h < HH && w < WWD) ? 16u : 0u;
                size_t eo = ((((size_t)b * HH + (h & 63)) * WWD + (w & 63)) * 64) + ci0q * 16 + c4 * 4;
                cpa16(xb + (uint32_t)pos * POS_STRIDE + c4 * 16,
                      (const char*)g_xh + eo * 4, sz);
            }
        }
    };
    auto stage_w = [&](int ci0q, int khw, int wb) {
        int co = tid >> 2, c4 = tid & 3;
        const char* src = (const char*)g_wbuf +
            (((size_t)(khw * COUT + co0 + co)) * CIN + ci0q * 32) * 2 + c4 * 16;
        cpa16(SW + (uint32_t)wb * WBUFSZ + (uint32_t)co * POS_STRIDE + c4 * 16, src, 16);
    };
    auto issue_unit = [&](int u) {
        if (u < 36) {
            int ci0q = u / 9, khw = u % 9;
            if (khw == 0) stage_x(ci0q);
            stage_w(ci0q, khw, u & 3);
        }
        asm volatile("cp.async.commit_group;" ::: "memory");  // always: keeps group count aligned
    };

    issue_unit(0);
    issue_unit(1);
    issue_unit(2);

    for (int it = 0; it < 36; it++) {
        asm volatile("cp.async.wait_group 2;" ::: "memory");
        __syncthreads();
        issue_unit(it + 3);

        const int ci0q = it / 9, khw = it % 9;
        const int kh = khw / 3, kw = khw % 3;
        const uint32_t xb = SX + (uint32_t)(ci0q & 1) * XBUFSZ;
        const uint32_t wb = SW + (uint32_t)(it & 3) * WBUFSZ;
        const uint32_t hwoff = (uint32_t)((wn + kh) * 66 + kw) * POS_STRIDE;

#pragma unroll
        for (int ci16 = 0; ci16 < 2; ci16++) {
            const uint32_t xsel = xb + ci16 * 32 + hwoff;
            const uint32_t wsel = wb + ci16 * 32;
            uint32_t a0[4], a1[4];
            ldsm_x4(a0, wsel + aoff0);
            ldsm_x4(a1, wsel + aoff1);
#pragma unroll
            for (int j = 0; j < 4; j++) {
                uint32_t bx[4];
                ldsm_x4(bx, xsel + qb[j]);
                MMA16816(acc[0][2 * j], a0, bx[0], bx[1]);
                MMA16816(acc[0][2 * j + 1], a0, bx[2], bx[3]);
                MMA16816(acc[1][2 * j], a1, bx[0], bx[1]);
                MMA16816(acc[1][2 * j + 1], a1, bx[2], bx[3]);
            }
        }
    }

    // ---- epilogue: direct float2 stores ----
    const int row = lid >> 2, qp = lid & 3;
    const int ho = ho0 + wn;
    if (ho < HOUT) {
#pragma unroll
        for (int mi = 0; mi < 2; mi++) {
            const int cor = co0 + wm * 32 + mi * 16 + row;
            float* b0p = out + (((size_t)b * COUT + cor) * HOUT + ho) * WOUT;
            float* b1p = out + (((size_t)b * COUT + cor + 8) * HOUT + ho) * WOUT;
#pragma unroll
            for (int ni = 0; ni < 8; ni++) {
                const int wo = ni * 8 + qp * 2;
                if (wo < WOUT) {
                    *(float2*)(b0p + wo) = make_float2(acc[mi][ni][0], acc[mi][ni][1]);
                    *(float2*)(b1p + wo) = make_float2(acc[mi][ni][2], acc[mi][ni][3]);
                }
            }
        }
    }
}

// ---------------- launch ----------------
extern "C" void kernel_launch(void* const* d_in, const int* in_sizes, int n_in,
                              void* d_out, int out_size) {
    const float* x = (const float*)d_in[0];
    const float* w = (const float*)d_in[1];
    float* out = (float*)d_out;

    prep_w_kernel<<<(9 * COUT * CIN + 255) / 256, 256>>>(w);
    prep_x_kernel<<<dim3(HH, BB), 256>>>(x);

    cudaFuncSetAttribute(xorconv_mma_kernel,
                         cudaFuncAttributeMaxDynamicSharedMemorySize, SMEM_TOTAL);
    xorconv_mma_kernel<<<dim3(16, 2, BB), 512, SMEM_TOTAL>>>(out);
}